// round 4
// baseline (speedup 1.0000x reference)
#include <cuda_runtime.h>

#define B_     4
#define S_     16
#define T_     16
#define DIM_   512
#define HSP    32
#define WSP    32
#define HW_    1024
#define HEADS_ 8
#define DH_    64

// ---------------- scratch (no allocations allowed) ----------------
__device__ float g_qm[B_*S_*DIM_];
__device__ float g_km[B_*T_*DIM_];
__device__ float g_qp[B_*S_*DIM_];
__device__ float g_kp[B_*T_*DIM_];
__device__ float g_attn[B_*HEADS_*S_*T_];

// ---------------- kernel 1: spatial means of q and k ----------------
// one warp per (b, s|t, d) row of 1024 contiguous floats
__global__ void mean_kernel(const float* __restrict__ q, const float* __restrict__ k) {
    int w    = blockIdx.x * (blockDim.x >> 5) + (threadIdx.x >> 5);
    int lane = threadIdx.x & 31;
    const int NROW = B_*S_*DIM_;          // 32768 rows each
    const float* src;
    float* dst;
    int r;
    if (w < NROW) { src = q; dst = g_qm; r = w; }
    else          { src = k; dst = g_km; r = w - NROW; }
    const float4* p = (const float4*)(src + (size_t)r * HW_);
    float s = 0.f;
#pragma unroll
    for (int i = 0; i < 8; i++) {
        float4 v4 = p[lane + i*32];
        s += v4.x + v4.y + v4.z + v4.w;
    }
#pragma unroll
    for (int m = 16; m; m >>= 1) s += __shfl_xor_sync(0xffffffffu, s, m);
    if (lane == 0) dst[r] = s * (1.f/1024.f);
}

// ---------------- kernel 2: row @ W.T projections ----------------
// 128 blocks (64 qm rows then 64 km rows), 512 threads, W tiled into smem
__global__ void proj_kernel(const float* __restrict__ Wq, const float* __restrict__ Wk) {
    __shared__ float rowS[DIM_];
    __shared__ float Ws[DIM_*17];
    int rr  = blockIdx.x;
    int tid = threadIdx.x;
    const float* W; const float* in; float* out; float scale;
    if (rr < 64) { in = g_qm + rr*DIM_;      W = Wq; out = g_qp + rr*DIM_;      scale = 0.125f; } // dh^-0.5
    else         { in = g_km + (rr-64)*DIM_; W = Wk; out = g_kp + (rr-64)*DIM_; scale = 1.f;    }
    rowS[tid] = in[tid];
    float acc = 0.f;
    for (int e0 = 0; e0 < DIM_; e0 += 16) {
        __syncthreads();
#pragma unroll
        for (int i = 0; i < 16; i++) {
            int idx = tid + i*512;
            int d = idx >> 4, e = idx & 15;
            Ws[d*17 + e] = W[d*DIM_ + e0 + e];
        }
        __syncthreads();
#pragma unroll
        for (int e = 0; e < 16; e++)
            acc += rowS[e0 + e] * Ws[tid*17 + e];
    }
    out[tid] = acc * scale;
}

// ---------------- kernel 3: logits + softmax -> attn[b,h,s,t] ----------------
__global__ void attn_kernel() {
    int blk  = blockIdx.x;               // B*HEADS*S = 512
    int b    = blk >> 7;
    int h    = (blk >> 4) & 7;
    int s    = blk & 15;
    int lane = threadIdx.x;
    int t    = lane & 15;                // both warp halves duplicate work
    const float* qr = g_qp + (size_t)(b*16 + s)*DIM_ + h*DH_;
    const float* kr = g_kp + (size_t)(b*16 + t)*DIM_ + h*DH_;
    float lg = 0.f;
#pragma unroll
    for (int j = 0; j < DH_; j++) lg += qr[j] * kr[j];
    float mx = lg;
#pragma unroll
    for (int m = 8; m; m >>= 1) mx = fmaxf(mx, __shfl_xor_sync(0xffffffffu, mx, m));
    float e = __expf(lg - mx);
    float sm = e;
#pragma unroll
    for (int m = 8; m; m >>= 1) sm += __shfl_xor_sync(0xffffffffu, sm, m);
    if (lane < 16) g_attn[((b*8 + h)*16 + s)*16 + t] = e / sm;
}

// ---------------- kernel 4: fused Wv GEMM + attention mix + transpose write ----------------
// Tile: M = 256 rows (16 t x 16 p, p = 4x4 spatial square), N = 64 (one head), K = 512.
// f32x2 packed FMA inner loop (pairs along M; Wv pre-duplicated in smem).
#define KC 16
#define AP 260    // As row stride, floats
#define BP 68     // Bs2 row stride, u64 entries
#define CP 68     // Cs row stride, floats
#define SMEM4 (256*CP*4)   // 69632 bytes (unions As/Bs2)

extern __shared__ char smraw[];

__global__ __launch_bounds__(256, 2)
void main_kernel(const float* __restrict__ v, const float* __restrict__ Wv,
                 float* __restrict__ out) {
    float* As               = (float*)smraw;                        // [KC][AP]
    unsigned long long* Bs2 = (unsigned long long*)(smraw + KC*AP*4); // [KC][BP]
    float* Cs               = (float*)smraw;                        // [256][CP] (union, used after mainloop)

    int tid = threadIdx.x;
    int b   = blockIdx.z;
    int h   = blockIdx.y;
    int tx  = blockIdx.x;
    int h0  = (tx >> 3) * 4;            // spatial tile origin (h_i)
    int w0  = (tx & 7) * 4;             // spatial tile origin (w_i)
    int tm  = tid & 31, tn = tid >> 5;
    int m0  = tm * 8,   n0 = tn * 8;

    unsigned long long acc2[4][8];
#pragma unroll
    for (int i = 0; i < 4; i++)
#pragma unroll
        for (int j = 0; j < 8; j++) acc2[i][j] = 0ull;

    for (int kc = 0; kc < DIM_; kc += KC) {
        __syncthreads();
        // A: v[b, t, kc+kk, (h0+hh)*32 + w0 .. w0+3]  -> As[kk][t*16 + hh*4 + ww]
#pragma unroll
        for (int i = 0; i < 4; i++) {
            int idx = tid + i*256;                 // 1024 float4 loads
            int kk = idx >> 6, m4 = idx & 63;
            int t  = m4 >> 2,  hh = m4 & 3;
            const float4* src = (const float4*)(v +
                ((size_t)((b*16 + t)*512 + kc + kk))*1024 + (h0 + hh)*32 + w0);
            *((float4*)&As[kk*AP + t*16 + hh*4]) = *src;
        }
        // B: Wv[h*64+n, kc+kq..] duplicated into packed pairs
        {
            int n  = tid >> 2;
            int kq = (tid & 3) * 4;
            float4 w4 = *(const float4*)(Wv + (size_t)(h*64 + n)*512 + kc + kq);
            unsigned int u0 = __float_as_uint(w4.x), u1 = __float_as_uint(w4.y);
            unsigned int u2 = __float_as_uint(w4.z), u3 = __float_as_uint(w4.w);
            Bs2[(kq+0)*BP + n] = ((unsigned long long)u0 << 32) | u0;
            Bs2[(kq+1)*BP + n] = ((unsigned long long)u1 << 32) | u1;
            Bs2[(kq+2)*BP + n] = ((unsigned long long)u2 << 32) | u2;
            Bs2[(kq+3)*BP + n] = ((unsigned long long)u3 << 32) | u3;
        }
        __syncthreads();
#pragma unroll
        for (int kk = 0; kk < KC; kk++) {
            unsigned long long a2[4], bb[8];
            const ulonglong2* ap = (const ulonglong2*)&As[kk*AP + m0];
            ulonglong2 av0 = ap[0], av1 = ap[1];
            a2[0] = av0.x; a2[1] = av0.y; a2[2] = av1.x; a2[3] = av1.y;
            const ulonglong2* bp = (const ulonglong2*)&Bs2[kk*BP + n0];
            ulonglong2 bv0 = bp[0], bv1 = bp[1], bv2 = bp[2], bv3 = bp[3];
            bb[0] = bv0.x; bb[1] = bv0.y; bb[2] = bv1.x; bb[3] = bv1.y;
            bb[4] = bv2.x; bb[5] = bv2.y; bb[6] = bv3.x; bb[7] = bv3.y;
#pragma unroll
            for (int i = 0; i < 4; i++)
#pragma unroll
                for (int j = 0; j < 8; j++)
                    asm("fma.rn.f32x2 %0, %1, %2, %0;"
                        : "+l"(acc2[i][j]) : "l"(a2[i]), "l"(bb[j]));
        }
    }

    __syncthreads();   // mainloop done reading As/Bs2; Cs aliases them
    // unpack accumulators into Cs[m][n]
#pragma unroll
    for (int i = 0; i < 4; i++) {
        float lo[8], hi[8];
#pragma unroll
        for (int j = 0; j < 8; j++) {
            lo[j] = __uint_as_float((unsigned int)(acc2[i][j] & 0xffffffffull));
            hi[j] = __uint_as_float((unsigned int)(acc2[i][j] >> 32));
        }
        int mlo = m0 + 2*i, mhi = mlo + 1;
        *((float4*)&Cs[mlo*CP + n0    ]) = make_float4(lo[0], lo[1], lo[2], lo[3]);
        *((float4*)&Cs[mlo*CP + n0 + 4]) = make_float4(lo[4], lo[5], lo[6], lo[7]);
        *((float4*)&Cs[mhi*CP + n0    ]) = make_float4(hi[0], hi[1], hi[2], hi[3]);
        *((float4*)&Cs[mhi*CP + n0 + 4]) = make_float4(hi[4], hi[5], hi[6], hi[7]);
    }
    __syncthreads();

    // epilogue: out[s, p_out, n] = sum_t attn[b,h,s,t] * Cs[t*16+pp][n]
    int sn = tid >> 4;
    int pg = tid & 15;
    int hh = pg & 3, ww = pg >> 2;
    int pp = hh*4 + ww;                  // matches loader's m encoding

    float wt[16];
#pragma unroll
    for (int t = 0; t < 16; t++) wt[t] = g_attn[((b*8 + h)*16 + sn)*16 + t];

    float acc[64];
#pragma unroll
    for (int n = 0; n < 64; n++) acc[n] = 0.f;
#pragma unroll
    for (int t = 0; t < 16; t++) {
        float w = wt[t];
        const float* crow = &Cs[(t*16 + pp)*CP];
#pragma unroll
        for (int n4 = 0; n4 < 16; n4++) {
            float4 c = *((const float4*)&crow[n4*4]);
            acc[n4*4+0] += w * c.x;
            acc[n4*4+1] += w * c.y;
            acc[n4*4+2] += w * c.z;
            acc[n4*4+3] += w * c.w;
        }
    }
    // output spatial index is the transpose of input spatial index:
    // pin = (h0+hh)*32 + (w0+ww)  ->  p_out = (w0+ww)*32 + (h0+hh)
    float* op = out + ((size_t)((b*16 + sn)*512 + h*64))*1024 + (w0 + ww)*32 + h0 + hh;
#pragma unroll
    for (int n = 0; n < 64; n++) op[(size_t)n*1024] = acc[n];
}

// ---------------- launcher ----------------
extern "C" void kernel_launch(void* const* d_in, const int* in_sizes, int n_in,
                              void* d_out, int out_size) {
    const float* q  = (const float*)d_in[0];
    const float* k  = (const float*)d_in[1];
    const float* v  = (const float*)d_in[2];
    const float* Wq = (const float*)d_in[3];
    const float* Wk = (const float*)d_in[4];
    const float* Wv = (const float*)d_in[5];
    float* out = (float*)d_out;

    cudaFuncSetAttribute(main_kernel, cudaFuncAttributeMaxDynamicSharedMemorySize, SMEM4);

    mean_kernel<<<8192, 256>>>(q, k);      // 65536 rows, 8 warps/block
    proj_kernel<<<128, 512>>>(Wq, Wk);
    attn_kernel<<<512, 32>>>();
    dim3 g4(64, HEADS_, B_);
    main_kernel<<<g4, 256, SMEM4>>>(v, Wv, out);
}

// round 6
// speedup vs baseline: 3.2750x; 3.2750x over previous
#include <cuda_runtime.h>
#include <cuda_bf16.h>
#include <cstdint>

#define B_     4
#define DIM_   512
#define HW_    1024

// ---------------- scratch ----------------
__device__ float g_qm[64*DIM_];
__device__ float g_km[64*DIM_];
__device__ float g_qp[64*DIM_];
__device__ float g_kp[64*DIM_];
__device__ float g_attn[B_*8*16*16];
__device__ __nv_bfloat16 g_wvh[DIM_*DIM_];
__device__ __nv_bfloat16 g_wvl[DIM_*DIM_];
__device__ __nv_bfloat16 g_vth[64ull*HW_*DIM_];   // [bt][p][k] bf16 hi
__device__ __nv_bfloat16 g_vtl[64ull*HW_*DIM_];   // [bt][p][k] bf16 lo

__device__ __forceinline__ uint32_t smem_u32(const void* p) {
    uint32_t a;
    asm("{ .reg .u64 t; cvta.to.shared.u64 t, %1; cvt.u32.u64 %0, t; }" : "=r"(a) : "l"(p));
    return a;
}
__device__ __forceinline__ void ldm_x4(uint32_t* r, uint32_t addr) {
    asm volatile("ldmatrix.sync.aligned.m8n8.x4.shared.b16 {%0,%1,%2,%3}, [%4];"
                 : "=r"(r[0]), "=r"(r[1]), "=r"(r[2]), "=r"(r[3]) : "r"(addr));
}
__device__ __forceinline__ void mma_bf16(float* c, const uint32_t* a, uint32_t b0, uint32_t b1) {
    asm volatile("mma.sync.aligned.m16n8k16.row.col.f32.bf16.bf16.f32 "
        "{%0,%1,%2,%3}, {%4,%5,%6,%7}, {%8,%9}, {%0,%1,%2,%3};"
        : "+f"(c[0]), "+f"(c[1]), "+f"(c[2]), "+f"(c[3])
        : "r"(a[0]), "r"(a[1]), "r"(a[2]), "r"(a[3]), "r"(b0), "r"(b1));
}

// ---------------- kernel 1: spatial means ----------------
__global__ void mean_kernel(const float* __restrict__ q, const float* __restrict__ k) {
    int w    = blockIdx.x * (blockDim.x >> 5) + (threadIdx.x >> 5);
    int lane = threadIdx.x & 31;
    const int NROW = 64*DIM_;
    const float* src; float* dst; int r;
    if (w < NROW) { src = q; dst = g_qm; r = w; }
    else          { src = k; dst = g_km; r = w - NROW; }
    const float4* p = (const float4*)(src + (size_t)r * HW_);
    float s = 0.f;
#pragma unroll
    for (int i = 0; i < 8; i++) { float4 v4 = p[lane + i*32]; s += v4.x + v4.y + v4.z + v4.w; }
#pragma unroll
    for (int m = 16; m; m >>= 1) s += __shfl_xor_sync(0xffffffffu, s, m);
    if (lane == 0) dst[r] = s * (1.f/1024.f);
}

// ---------------- kernel 2: pooled projections ----------------
__global__ void proj_kernel(const float* __restrict__ Wq, const float* __restrict__ Wk) {
    __shared__ float rowS[DIM_];
    __shared__ float Ws[DIM_*17];
    int rr  = blockIdx.x;
    int tid = threadIdx.x;
    const float* W; const float* in; float* out; float scale;
    if (rr < 64) { in = g_qm + rr*DIM_;      W = Wq; out = g_qp + rr*DIM_;      scale = 0.125f; }
    else         { in = g_km + (rr-64)*DIM_; W = Wk; out = g_kp + (rr-64)*DIM_; scale = 1.f;    }
    rowS[tid] = in[tid];
    float acc = 0.f;
    for (int e0 = 0; e0 < DIM_; e0 += 16) {
        __syncthreads();
#pragma unroll
        for (int i = 0; i < 16; i++) {
            int idx = tid + i*512;
            int d = idx >> 4, e = idx & 15;
            Ws[d*17 + e] = W[d*DIM_ + e0 + e];
        }
        __syncthreads();
#pragma unroll
        for (int e = 0; e < 16; e++) acc += rowS[e0 + e] * Ws[tid*17 + e];
    }
    out[tid] = acc * scale;
}

// ---------------- kernel 3: softmax ----------------
__global__ void attn_kernel() {
    int blk = blockIdx.x;
    int b = blk >> 7, h = (blk >> 4) & 7, s = blk & 15;
    int lane = threadIdx.x, t = lane & 15;
    const float* qr = g_qp + (size_t)(b*16 + s)*DIM_ + h*64;
    const float* kr = g_kp + (size_t)(b*16 + t)*DIM_ + h*64;
    float lg = 0.f;
#pragma unroll
    for (int j = 0; j < 64; j++) lg += qr[j] * kr[j];
    float mx = lg;
#pragma unroll
    for (int m = 8; m; m >>= 1) mx = fmaxf(mx, __shfl_xor_sync(0xffffffffu, mx, m));
    float e = __expf(lg - mx);
    float sm = e;
#pragma unroll
    for (int m = 8; m; m >>= 1) sm += __shfl_xor_sync(0xffffffffu, sm, m);
    if (lane < 16) g_attn[((b*8 + h)*16 + s)*16 + t] = e / sm;
}

// ---------------- kernel 4: Wv -> bf16 hi/lo ----------------
__global__ void wvsplit_kernel(const float* __restrict__ Wv) {
    int idx = blockIdx.x * 512 + threadIdx.x;
    float x = Wv[idx];
    __nv_bfloat16 h = __float2bfloat16(x);
    g_wvh[idx] = h;
    g_wvl[idx] = __float2bfloat16(x - __bfloat162float(h));
}

// ---------------- kernel 5: v transpose + bf16 hi/lo split ----------------
__global__ __launch_bounds__(256) void convert_kernel(const float* __restrict__ v) {
    __shared__ float st[64*65];
    int pb = blockIdx.x, kb = blockIdx.y, bt = blockIdx.z;
#pragma unroll
    for (int i = 0; i < 4; i++) {
        int idx = threadIdx.x + i*256;
        int kk = idx >> 4, p4 = (idx & 15) * 4;
        float4 x = *(const float4*)(v + ((size_t)(bt*512 + kb*64 + kk))*HW_ + pb*64 + p4);
        st[kk*65 + p4 + 0] = x.x; st[kk*65 + p4 + 1] = x.y;
        st[kk*65 + p4 + 2] = x.z; st[kk*65 + p4 + 3] = x.w;
    }
    __syncthreads();
#pragma unroll
    for (int it = 0; it < 2; it++) {
        int task = threadIdx.x + it*256;
        int p = task >> 3, kg = task & 7;
        unsigned int hw[4], lw[4];
#pragma unroll
        for (int j = 0; j < 4; j++) {
            float x0 = st[(kg*8 + 2*j    )*65 + p];
            float x1 = st[(kg*8 + 2*j + 1)*65 + p];
            __nv_bfloat16 h0 = __float2bfloat16(x0), h1 = __float2bfloat16(x1);
            __nv_bfloat16 l0 = __float2bfloat16(x0 - __bfloat162float(h0));
            __nv_bfloat16 l1 = __float2bfloat16(x1 - __bfloat162float(h1));
            hw[j] = ((unsigned)__bfloat16_as_ushort(h1) << 16) | __bfloat16_as_ushort(h0);
            lw[j] = ((unsigned)__bfloat16_as_ushort(l1) << 16) | __bfloat16_as_ushort(l0);
        }
        size_t e = ((size_t)(bt*HW_ + pb*64 + p))*DIM_ + kb*64 + kg*8;
        *(uint4*)(g_vth + e) = make_uint4(hw[0], hw[1], hw[2], hw[3]);
        *(uint4*)(g_vtl + e) = make_uint4(lw[0], lw[1], lw[2], lw[3]);
    }
}

// ---------------- kernel 6: warp-mma GEMM + fused mix + transpose write ----------------
// CTA: M=128 d x N=128 (16t x 8p: pp = ww*4+hh, 4x2 spatial tile) x K=512, 3 split terms.
// smem buffers: Ah@0 Al@16K Bh@32K Bl@48K, 128 rows x 128B, XOR-swizzled blocks.
// Epilogue: Cs[n=128][132] fp32 aliases buffers.
#define DSMEM (132*128*4)
extern __shared__ char dsm[];

__device__ __forceinline__ uint32_t sw_addr(uint32_t base, int row, int blk) {
    return base + row*128 + (((uint32_t)(blk ^ (row & 7))) << 4);
}

__global__ __launch_bounds__(256, 2) void gemm_kernel(float* __restrict__ out) {
    __shared__ float s_attnT[512];   // [hl(2)][t*16+s]
    int tid = threadIdx.x, lane = tid & 31, wid = tid >> 5;
    int md = blockIdx.x & 3;                 // d-tile (fastest -> v L2 reuse)
    int px = blockIdx.x >> 2;                // 0..127 spatial tile
    int b  = blockIdx.y;
    int sh0 = (px & 7) * 4, sw0 = (px >> 3) * 2;
    int d0 = md * 128;

    uint32_t sb = smem_u32(dsm);

    // attn transposed: s_attnT[hl*256 + t*16 + s] = attn[b, 2md+hl, s, t]
#pragma unroll
    for (int i = 0; i < 2; i++) {
        int idx = tid + i*256;
        int hl = idx >> 8, tt = (idx >> 4) & 15, ss = idx & 15;
        s_attnT[idx] = g_attn[((b*8 + md*2 + hl)*16 + ss)*16 + tt];
    }

    // per-thread load offsets (element units), fixed across chunks
    int aoff[4], boff[4], soff[4];
#pragma unroll
    for (int i = 0; i < 4; i++) {
        int idx = tid + i*256;               // 0..1023
        int r = idx >> 3, c = idx & 7;
        aoff[i] = (d0 + r)*DIM_ + c*8;
        int t = r >> 3, pp = r & 7, ww = pp >> 2, hh = pp & 3;
        int pin = (sh0 + hh)*32 + (sw0 + ww);
        boff[i] = ((b*16 + t)*HW_ + pin)*DIM_ + c*8;
        soff[i] = r*128 + ((c ^ (r & 7)) << 4);
    }

    int m0w = (wid & 3) * 32;
    int n0w = (wid >> 2) * 64;
    float acc[2][8][4];
#pragma unroll
    for (int mt = 0; mt < 2; mt++)
#pragma unroll
        for (int nt = 0; nt < 8; nt++)
#pragma unroll
            for (int j = 0; j < 4; j++) acc[mt][nt][j] = 0.f;

#pragma unroll 1
    for (int c8 = 0; c8 < 8; c8++) {
        int kc = c8 * 64;
        if (c8) __syncthreads();             // mma done with previous buffer
#pragma unroll
        for (int i = 0; i < 4; i++) {
            *(uint4*)(dsm +         soff[i]) = *(const uint4*)(g_wvh + aoff[i] + kc);
            *(uint4*)(dsm + 16384 + soff[i]) = *(const uint4*)(g_wvl + aoff[i] + kc);
            *(uint4*)(dsm + 32768 + soff[i]) = *(const uint4*)(g_vth + boff[i] + kc);
            *(uint4*)(dsm + 49152 + soff[i]) = *(const uint4*)(g_vtl + boff[i] + kc);
        }
        __syncthreads();
#pragma unroll
        for (int ks = 0; ks < 4; ks++) {
            int kb = ks * 2;
            uint32_t ah[2][4], al[2][4];
            // A ldmatrix: lanes 0-15 -> rows base+(lane&15) blk kb; 16-31 -> blk kb+1
            int arow_l = (lane & 15);
            int ablk   = kb + (lane >> 4);
#pragma unroll
            for (int mt = 0; mt < 2; mt++) {
                int row = m0w + mt*16 + arow_l;
                ldm_x4(ah[mt], sw_addr(sb,         row, ablk));
                ldm_x4(al[mt], sw_addr(sb + 16384, row, ablk));
            }
            // B: lanes: row = base_n + (lane&7) + ((lane&16)?8:0); blk = kb + ((lane>>3)&1)
            int brow_l = (lane & 7) + ((lane & 16) ? 8 : 0);
            int bblk   = kb + ((lane >> 3) & 1);
#pragma unroll
            for (int ntp = 0; ntp < 4; ntp++) {
                int row = n0w + ntp*16 + brow_l;
                uint32_t bh[4], bl[4];
                ldm_x4(bh, sw_addr(sb + 32768, row, bblk));
                ldm_x4(bl, sw_addr(sb + 49152, row, bblk));
#pragma unroll
                for (int mt = 0; mt < 2; mt++) {
                    mma_bf16(acc[mt][2*ntp  ], ah[mt], bh[0], bh[1]);
                    mma_bf16(acc[mt][2*ntp  ], ah[mt], bl[0], bl[1]);
                    mma_bf16(acc[mt][2*ntp  ], al[mt], bh[0], bh[1]);
                    mma_bf16(acc[mt][2*ntp+1], ah[mt], bh[2], bh[3]);
                    mma_bf16(acc[mt][2*ntp+1], ah[mt], bl[2], bl[3]);
                    mma_bf16(acc[mt][2*ntp+1], al[mt], bh[2], bh[3]);
                }
            }
        }
    }
    __syncthreads();                          // buffers dead; alias Cs

    // store accumulators: Cs[n][d], stride 132
    float* Cs = (float*)dsm;
    int g = lane >> 2, tig = lane & 3;
#pragma unroll
    for (int mt = 0; mt < 2; mt++)
#pragma unroll
        for (int nt = 0; nt < 8; nt++) {
            int m = m0w + mt*16 + g;
            int n = n0w + nt*8 + 2*tig;
            Cs[n*132 + m]           = acc[mt][nt][0];
            Cs[(n+1)*132 + m]       = acc[mt][nt][1];
            Cs[n*132 + m + 8]       = acc[mt][nt][2];
            Cs[(n+1)*132 + m + 8]   = acc[mt][nt][3];
        }
    __syncthreads();

    // mix epilogue: thread = (d, ww); acc over t with f32x2 pairs on hh
    {
        int d = tid & 127, ww = tid >> 7;
        int hl = d >> 6;
        const float* at = s_attnT + hl*256;
        unsigned long long ap[16][2];
#pragma unroll
        for (int s = 0; s < 16; s++) { ap[s][0] = 0ull; ap[s][1] = 0ull; }
#pragma unroll
        for (int t = 0; t < 16; t++) {
            float c0 = Cs[(t*8 + ww*4 + 0)*132 + d];
            float c1 = Cs[(t*8 + ww*4 + 1)*132 + d];
            float c2 = Cs[(t*8 + ww*4 + 2)*132 + d];
            float c3 = Cs[(t*8 + ww*4 + 3)*132 + d];
            unsigned long long cv01 = ((unsigned long long)__float_as_uint(c1) << 32) | __float_as_uint(c0);
            unsigned long long cv23 = ((unsigned long long)__float_as_uint(c3) << 32) | __float_as_uint(c2);
#pragma unroll
            for (int s = 0; s < 16; s++) {
                unsigned int wu = __float_as_uint(at[t*16 + s]);
                unsigned long long w2 = ((unsigned long long)wu << 32) | wu;
                asm("fma.rn.f32x2 %0, %1, %2, %0;" : "+l"(ap[s][0]) : "l"(cv01), "l"(w2));
                asm("fma.rn.f32x2 %0, %1, %2, %0;" : "+l"(ap[s][1]) : "l"(cv23), "l"(w2));
            }
        }
        // out[b,s, d0+d, (sw0+ww)*32 + sh0 + hh], hh contiguous -> float4
        float* op = out + ((size_t)(b*16)*512 + d0 + d)*HW_ + (sw0 + ww)*32 + sh0;
#pragma unroll
        for (int s = 0; s < 16; s++) {
            float4 v4;
            v4.x = __uint_as_float((unsigned int)(ap[s][0] & 0xffffffffull));
            v4.y = __uint_as_float((unsigned int)(ap[s][0] >> 32));
            v4.z = __uint_as_float((unsigned int)(ap[s][1] & 0xffffffffull));
            v4.w = __uint_as_float((unsigned int)(ap[s][1] >> 32));
            *(float4*)(op + (size_t)s*512*HW_) = v4;
        }
    }
}

// ---------------- launcher ----------------
extern "C" void kernel_launch(void* const* d_in, const int* in_sizes, int n_in,
                              void* d_out, int out_size) {
    const float* q  = (const float*)d_in[0];
    const float* k  = (const float*)d_in[1];
    const float* v  = (const float*)d_in[2];
    const float* Wq = (const float*)d_in[3];
    const float* Wk = (const float*)d_in[4];
    const float* Wv = (const float*)d_in[5];
    float* out = (float*)d_out;

    cudaFuncSetAttribute(gemm_kernel, cudaFuncAttributeMaxDynamicSharedMemorySize, DSMEM);

    mean_kernel<<<8192, 256>>>(q, k);
    proj_kernel<<<128, 512>>>(Wq, Wk);
    attn_kernel<<<512, 32>>>();
    wvsplit_kernel<<<512, 512>>>(Wv);
    dim3 gc(16, 8, 64);
    convert_kernel<<<gc, 256>>>(v);
    dim3 gg(512, 4);
    gemm_kernel<<<gg, 256, DSMEM>>>(out);
}

// round 7
// speedup vs baseline: 4.9292x; 1.5051x over previous
#include <cuda_runtime.h>
#include <cuda_bf16.h>
#include <cstdint>

#define B_     4
#define DIM_   512
#define HW_    1024

// ---------------- scratch ----------------
__device__ float g_qm[64*DIM_];
__device__ float g_km[64*DIM_];
__device__ float g_qp[64*DIM_];
__device__ float g_kp[64*DIM_];
__device__ float g_attn[B_*8*16*16];
// interleaved split storage: per row, 16 chunks x [32 hi | 32 lo] bf16
__device__ __nv_bfloat16 g_wvs[DIM_*1024];            // [d][ch][hi32|lo32]
__device__ __nv_bfloat16 g_vs[64ull*HW_*1024];        // [bt][p][ch][hi32|lo32]

__device__ __forceinline__ uint32_t smem_u32(const void* p) {
    uint32_t a;
    asm("{ .reg .u64 t; cvta.to.shared.u64 t, %1; cvt.u32.u64 %0, t; }" : "=r"(a) : "l"(p));
    return a;
}
__device__ __forceinline__ void ldm_x4(uint32_t* r, uint32_t addr) {
    asm volatile("ldmatrix.sync.aligned.m8n8.x4.shared.b16 {%0,%1,%2,%3}, [%4];"
                 : "=r"(r[0]), "=r"(r[1]), "=r"(r[2]), "=r"(r[3]) : "r"(addr));
}
__device__ __forceinline__ void mma_bf16(float* c, const uint32_t* a, uint32_t b0, uint32_t b1) {
    asm volatile("mma.sync.aligned.m16n8k16.row.col.f32.bf16.bf16.f32 "
        "{%0,%1,%2,%3}, {%4,%5,%6,%7}, {%8,%9}, {%0,%1,%2,%3};"
        : "+f"(c[0]), "+f"(c[1]), "+f"(c[2]), "+f"(c[3])
        : "r"(a[0]), "r"(a[1]), "r"(a[2]), "r"(a[3]), "r"(b0), "r"(b1));
}
__device__ __forceinline__ void cpa16(uint32_t d, const __nv_bfloat16* s) {
    asm volatile("cp.async.cg.shared.global [%0], [%1], 16;"
                 :: "r"(d), "l"(__cvta_generic_to_global(s)));
}
#define CP_COMMIT() asm volatile("cp.async.commit_group;" ::: "memory")
#define CP_WAIT2()  asm volatile("cp.async.wait_group 2;" ::: "memory")

// ---------------- kernel 1: spatial means ----------------
__global__ void mean_kernel(const float* __restrict__ q, const float* __restrict__ k) {
    int w    = blockIdx.x * (blockDim.x >> 5) + (threadIdx.x >> 5);
    int lane = threadIdx.x & 31;
    const int NROW = 64*DIM_;
    const float* src; float* dst; int r;
    if (w < NROW) { src = q; dst = g_qm; r = w; }
    else          { src = k; dst = g_km; r = w - NROW; }
    const float4* p = (const float4*)(src + (size_t)r * HW_);
    float s = 0.f;
#pragma unroll
    for (int i = 0; i < 8; i++) { float4 v4 = p[lane + i*32]; s += v4.x + v4.y + v4.z + v4.w; }
#pragma unroll
    for (int m = 16; m; m >>= 1) s += __shfl_xor_sync(0xffffffffu, s, m);
    if (lane == 0) dst[r] = s * (1.f/1024.f);
}

// ---------------- kernel 2: pooled projections ----------------
__global__ void proj_kernel(const float* __restrict__ Wq, const float* __restrict__ Wk) {
    __shared__ float rowS[DIM_];
    __shared__ float Ws[DIM_*17];
    int rr  = blockIdx.x;
    int tid = threadIdx.x;
    const float* W; const float* in; float* out; float scale;
    if (rr < 64) { in = g_qm + rr*DIM_;      W = Wq; out = g_qp + rr*DIM_;      scale = 0.125f; }
    else         { in = g_km + (rr-64)*DIM_; W = Wk; out = g_kp + (rr-64)*DIM_; scale = 1.f;    }
    rowS[tid] = in[tid];
    float acc = 0.f;
    for (int e0 = 0; e0 < DIM_; e0 += 16) {
        __syncthreads();
#pragma unroll
        for (int i = 0; i < 16; i++) {
            int idx = tid + i*512;
            int d = idx >> 4, e = idx & 15;
            Ws[d*17 + e] = W[d*DIM_ + e0 + e];
        }
        __syncthreads();
#pragma unroll
        for (int e = 0; e < 16; e++) acc += rowS[e0 + e] * Ws[tid*17 + e];
    }
    out[tid] = acc * scale;
}

// ---------------- kernel 3: softmax ----------------
__global__ void attn_kernel() {
    int blk = blockIdx.x;
    int b = blk >> 7, h = (blk >> 4) & 7, s = blk & 15;
    int lane = threadIdx.x, t = lane & 15;
    const float* qr = g_qp + (size_t)(b*16 + s)*DIM_ + h*64;
    const float* kr = g_kp + (size_t)(b*16 + t)*DIM_ + h*64;
    float lg = 0.f;
#pragma unroll
    for (int j = 0; j < 64; j++) lg += qr[j] * kr[j];
    float mx = lg;
#pragma unroll
    for (int m = 8; m; m >>= 1) mx = fmaxf(mx, __shfl_xor_sync(0xffffffffu, mx, m));
    float e = __expf(lg - mx);
    float sm = e;
#pragma unroll
    for (int m = 8; m; m >>= 1) sm += __shfl_xor_sync(0xffffffffu, sm, m);
    if (lane < 16) g_attn[((b*8 + h)*16 + s)*16 + t] = e / sm;
}

// ---------------- kernel 4: Wv -> interleaved bf16 hi/lo ----------------
__global__ void wvsplit_kernel(const float* __restrict__ Wv) {
    int g  = blockIdx.x * 512 + threadIdx.x;       // 0..32767
    int d  = g >> 6, k8 = (g & 63) * 8;
    const float* src = Wv + d*512 + k8;
    unsigned int hw[4], lw[4];
#pragma unroll
    for (int j = 0; j < 4; j++) {
        float x0 = src[2*j], x1 = src[2*j+1];
        __nv_bfloat16 h0 = __float2bfloat16(x0), h1 = __float2bfloat16(x1);
        __nv_bfloat16 l0 = __float2bfloat16(x0 - __bfloat162float(h0));
        __nv_bfloat16 l1 = __float2bfloat16(x1 - __bfloat162float(h1));
        hw[j] = ((unsigned)__bfloat16_as_ushort(h1) << 16) | __bfloat16_as_ushort(h0);
        lw[j] = ((unsigned)__bfloat16_as_ushort(l1) << 16) | __bfloat16_as_ushort(l0);
    }
    size_t e = (size_t)d*1024 + (k8 >> 5)*64 + (k8 & 31);
    *(uint4*)(g_wvs + e)      = make_uint4(hw[0], hw[1], hw[2], hw[3]);
    *(uint4*)(g_wvs + e + 32) = make_uint4(lw[0], lw[1], lw[2], lw[3]);
}

// ---------------- kernel 5: v transpose + interleaved bf16 hi/lo ----------------
__global__ __launch_bounds__(256) void convert_kernel(const float* __restrict__ v) {
    __shared__ float st[64*65];
    int pb = blockIdx.x, kb = blockIdx.y, bt = blockIdx.z;
#pragma unroll
    for (int i = 0; i < 4; i++) {
        int idx = threadIdx.x + i*256;
        int kk = idx >> 4, p4 = (idx & 15) * 4;
        float4 x = *(const float4*)(v + ((size_t)(bt*512 + kb*64 + kk))*HW_ + pb*64 + p4);
        st[kk*65 + p4 + 0] = x.x; st[kk*65 + p4 + 1] = x.y;
        st[kk*65 + p4 + 2] = x.z; st[kk*65 + p4 + 3] = x.w;
    }
    __syncthreads();
#pragma unroll
    for (int it = 0; it < 2; it++) {
        int task = threadIdx.x + it*256;
        int p = task >> 3, kg = task & 7;
        unsigned int hw[4], lw[4];
#pragma unroll
        for (int j = 0; j < 4; j++) {
            float x0 = st[(kg*8 + 2*j    )*65 + p];
            float x1 = st[(kg*8 + 2*j + 1)*65 + p];
            __nv_bfloat16 h0 = __float2bfloat16(x0), h1 = __float2bfloat16(x1);
            __nv_bfloat16 l0 = __float2bfloat16(x0 - __bfloat162float(h0));
            __nv_bfloat16 l1 = __float2bfloat16(x1 - __bfloat162float(h1));
            hw[j] = ((unsigned)__bfloat16_as_ushort(h1) << 16) | __bfloat16_as_ushort(h0);
            lw[j] = ((unsigned)__bfloat16_as_ushort(l1) << 16) | __bfloat16_as_ushort(l0);
        }
        int ch  = kb*2 + (kg >> 2);
        int pos = (kg & 3) * 8;
        size_t e = ((size_t)(bt*HW_ + pb*64 + p))*1024 + ch*64 + pos;
        *(uint4*)(g_vs + e)      = make_uint4(hw[0], hw[1], hw[2], hw[3]);
        *(uint4*)(g_vs + e + 32) = make_uint4(lw[0], lw[1], lw[2], lw[3]);
    }
}

// ---------------- kernel 6: pipelined warp-mma GEMM + fused mix ----------------
// CTA: M=128 d x N=128 (16t x 8p) x K=512 in 16 chunks of 32, 3-stage cp.async.
// Stage (32KB): A[128r x 128B(hi|lo)] @0, B @16KB. Cs[128n][132] fp32 aliases stages.
#define STG 32768
#define DSMEM (3*STG)
extern __shared__ char dsm[];

__global__ __launch_bounds__(256, 2) void gemm_kernel(float* __restrict__ out) {
    __shared__ float s_attnT[512];
    int tid = threadIdx.x, lane = tid & 31, wid = tid >> 5;
    int md = blockIdx.x & 3;
    int px = blockIdx.x >> 2;
    int b  = blockIdx.y;
    int sh0 = (px & 7) * 4, sw0 = (px >> 3) * 2;
    int d0 = md * 128;

    uint32_t sb = smem_u32(dsm);

#pragma unroll
    for (int i = 0; i < 2; i++) {
        int idx = tid + i*256;
        int hl = idx >> 8, tt = (idx >> 4) & 15, ss = idx & 15;
        s_attnT[idx] = g_attn[((b*8 + md*2 + hl)*16 + ss)*16 + tt];
    }

    // per-thread load offsets (bf16-element units into g_wvs/g_vs), fixed; +64/chunk
    int soffv[4], aoff[4], boff[4];
#pragma unroll
    for (int i = 0; i < 4; i++) {
        int idx = tid + i*256;               // 0..1023
        int r = idx >> 3, c = idx & 7;
        soffv[i] = r*128 + ((c ^ (r & 7)) << 4);
        aoff[i]  = (d0 + r)*1024 + c*8;
        int t = r >> 3, pp = r & 7, ww = pp >> 2, hh = pp & 3;
        int pin = (sh0 + hh)*32 + (sw0 + ww);
        boff[i]  = ((b*16 + t)*HW_ + pin)*1024 + c*8;
    }

    int m0w = (wid & 3) * 32;
    int n0w = (wid >> 2) * 64;
    float acc[2][8][4];
#pragma unroll
    for (int mt = 0; mt < 2; mt++)
#pragma unroll
        for (int nt = 0; nt < 8; nt++)
#pragma unroll
            for (int j = 0; j < 4; j++) acc[mt][nt][j] = 0.f;

    // prologue: issue chunks 0..2
#pragma unroll
    for (int c = 0; c < 3; c++) {
        uint32_t sa = sb + c*STG;
#pragma unroll
        for (int i = 0; i < 4; i++) {
            cpa16(sa +         soffv[i], g_wvs + aoff[i] + c*64);
            cpa16(sa + 16384 + soffv[i], g_vs  + boff[i] + c*64);
        }
        CP_COMMIT();
    }

    int stg = 0;
#pragma unroll 1
    for (int c = 0; c < 16; c++) {
        CP_WAIT2();
        __syncthreads();
        uint32_t sa  = sb + stg*STG;
        uint32_t sbb = sa + 16384;
#pragma unroll
        for (int ks = 0; ks < 2; ks++) {
            int kb = ks * 2;
            uint32_t ah[2][4], al[2][4];
            int arow_l = lane & 15;
            int asel   = lane >> 4;
#pragma unroll
            for (int mt = 0; mt < 2; mt++) {
                int row = m0w + mt*16 + arow_l;
                uint32_t rb = sa + row*128;
                ldm_x4(ah[mt], rb + ((((kb + asel)    ) ^ (row & 7)) << 4));
                ldm_x4(al[mt], rb + ((((kb + asel) + 4) ^ (row & 7)) << 4));
            }
            int brow_l = (lane & 7) + ((lane & 16) ? 8 : 0);
            int bsel   = (lane >> 3) & 1;
#pragma unroll
            for (int ntp = 0; ntp < 4; ntp++) {
                int row = n0w + ntp*16 + brow_l;
                uint32_t rb = sbb + row*128;
                uint32_t bh[4], bl[4];
                ldm_x4(bh, rb + ((((kb + bsel)    ) ^ (row & 7)) << 4));
                ldm_x4(bl, rb + ((((kb + bsel) + 4) ^ (row & 7)) << 4));
#pragma unroll
                for (int mt = 0; mt < 2; mt++) {
                    mma_bf16(acc[mt][2*ntp  ], ah[mt], bh[0], bh[1]);
                    mma_bf16(acc[mt][2*ntp  ], ah[mt], bl[0], bl[1]);
                    mma_bf16(acc[mt][2*ntp  ], al[mt], bh[0], bh[1]);
                    mma_bf16(acc[mt][2*ntp+1], ah[mt], bh[2], bh[3]);
                    mma_bf16(acc[mt][2*ntp+1], ah[mt], bl[2], bl[3]);
                    mma_bf16(acc[mt][2*ntp+1], al[mt], bh[2], bh[3]);
                }
            }
        }
        __syncthreads();
        if (c + 3 < 16) {
            uint32_t sd = sb + stg*STG;
#pragma unroll
            for (int i = 0; i < 4; i++) {
                cpa16(sd +         soffv[i], g_wvs + aoff[i] + (c+3)*64);
                cpa16(sd + 16384 + soffv[i], g_vs  + boff[i] + (c+3)*64);
            }
        }
        CP_COMMIT();
        stg = (stg + 1) == 3 ? 0 : stg + 1;
    }

    // store accumulators: Cs[n][d], stride 132 (aliases stage buffers)
    float* Cs = (float*)dsm;
    int g = lane >> 2, tig = lane & 3;
#pragma unroll
    for (int mt = 0; mt < 2; mt++)
#pragma unroll
        for (int nt = 0; nt < 8; nt++) {
            int m = m0w + mt*16 + g;
            int n = n0w + nt*8 + 2*tig;
            Cs[n*132 + m]         = acc[mt][nt][0];
            Cs[(n+1)*132 + m]     = acc[mt][nt][1];
            Cs[n*132 + m + 8]     = acc[mt][nt][2];
            Cs[(n+1)*132 + m + 8] = acc[mt][nt][3];
        }
    __syncthreads();

    // mix epilogue
    {
        int d = tid & 127, ww = tid >> 7;
        int hl = d >> 6;
        const float* at = s_attnT + hl*256;
        unsigned long long ap[16][2];
#pragma unroll
        for (int s = 0; s < 16; s++) { ap[s][0] = 0ull; ap[s][1] = 0ull; }
#pragma unroll
        for (int t = 0; t < 16; t++) {
            float c0 = Cs[(t*8 + ww*4 + 0)*132 + d];
            float c1 = Cs[(t*8 + ww*4 + 1)*132 + d];
            float c2 = Cs[(t*8 + ww*4 + 2)*132 + d];
            float c3 = Cs[(t*8 + ww*4 + 3)*132 + d];
            unsigned long long cv01 = ((unsigned long long)__float_as_uint(c1) << 32) | __float_as_uint(c0);
            unsigned long long cv23 = ((unsigned long long)__float_as_uint(c3) << 32) | __float_as_uint(c2);
#pragma unroll
            for (int s = 0; s < 16; s++) {
                unsigned int wu = __float_as_uint(at[t*16 + s]);
                unsigned long long w2 = ((unsigned long long)wu << 32) | wu;
                asm("fma.rn.f32x2 %0, %1, %2, %0;" : "+l"(ap[s][0]) : "l"(cv01), "l"(w2));
                asm("fma.rn.f32x2 %0, %1, %2, %0;" : "+l"(ap[s][1]) : "l"(cv23), "l"(w2));
            }
        }
        float* op = out + ((size_t)(b*16)*512 + d0 + d)*HW_ + (sw0 + ww)*32 + sh0;
#pragma unroll
        for (int s = 0; s < 16; s++) {
            float4 v4;
            v4.x = __uint_as_float((unsigned int)(ap[s][0] & 0xffffffffull));
            v4.y = __uint_as_float((unsigned int)(ap[s][0] >> 32));
            v4.z = __uint_as_float((unsigned int)(ap[s][1] & 0xffffffffull));
            v4.w = __uint_as_float((unsigned int)(ap[s][1] >> 32));
            *(float4*)(op + (size_t)s*512*HW_) = v4;
        }
    }
}

// ---------------- launcher ----------------
extern "C" void kernel_launch(void* const* d_in, const int* in_sizes, int n_in,
                              void* d_out, int out_size) {
    const float* q  = (const float*)d_in[0];
    const float* k  = (const float*)d_in[1];
    const float* v  = (const float*)d_in[2];
    const float* Wq = (const float*)d_in[3];
    const float* Wk = (const float*)d_in[4];
    const float* Wv = (const float*)d_in[5];
    float* out = (float*)d_out;

    cudaFuncSetAttribute(gemm_kernel, cudaFuncAttributeMaxDynamicSharedMemorySize, DSMEM);

    mean_kernel<<<8192, 256>>>(q, k);
    proj_kernel<<<128, 512>>>(Wq, Wk);
    attn_kernel<<<512, 32>>>();
    wvsplit_kernel<<<64, 512>>>(Wv);
    dim3 gc(16, 8, 64);
    convert_kernel<<<gc, 256>>>(v);
    dim3 gg(512, 4);
    gemm_kernel<<<gg, 256, DSMEM>>>(out);
}

// round 8
// speedup vs baseline: 5.8026x; 1.1772x over previous
#include <cuda_runtime.h>
#include <cuda_bf16.h>
#include <cuda_fp16.h>
#include <cstdint>

#define B_     4
#define DIM_   512
#define HW_    1024

// ---------------- scratch ----------------
__device__ float g_qm[64*DIM_];
__device__ float g_km[64*DIM_];
__device__ float g_qp[64*DIM_];
__device__ float g_kp[64*DIM_];
__device__ float g_attn[B_*8*16*16];
// Wv fp16 split, interleaved per 64-k chunk: [d][ch(8)][hi64|lo64]
__device__ __half g_wvs[DIM_*1024];
// v fp16 single: [bt][p][k]
__device__ __half g_vs[64ull*HW_*DIM_];

__device__ __forceinline__ uint32_t smem_u32(const void* p) {
    uint32_t a;
    asm("{ .reg .u64 t; cvta.to.shared.u64 t, %1; cvt.u32.u64 %0, t; }" : "=r"(a) : "l"(p));
    return a;
}
__device__ __forceinline__ void ldm_x4(uint32_t* r, uint32_t addr) {
    asm volatile("ldmatrix.sync.aligned.m8n8.x4.shared.b16 {%0,%1,%2,%3}, [%4];"
                 : "=r"(r[0]), "=r"(r[1]), "=r"(r[2]), "=r"(r[3]) : "r"(addr));
}
__device__ __forceinline__ void mma_f16(float* c, const uint32_t* a, uint32_t b0, uint32_t b1) {
    asm volatile("mma.sync.aligned.m16n8k16.row.col.f32.f16.f16.f32 "
        "{%0,%1,%2,%3}, {%4,%5,%6,%7}, {%8,%9}, {%0,%1,%2,%3};"
        : "+f"(c[0]), "+f"(c[1]), "+f"(c[2]), "+f"(c[3])
        : "r"(a[0]), "r"(a[1]), "r"(a[2]), "r"(a[3]), "r"(b0), "r"(b1));
}
__device__ __forceinline__ void cpa16(uint32_t d, const void* s) {
    asm volatile("cp.async.cg.shared.global [%0], [%1], 16;"
                 :: "r"(d), "l"(__cvta_generic_to_global(s)));
}
#define CP_COMMIT() asm volatile("cp.async.commit_group;" ::: "memory")
#define CP_WAIT1()  asm volatile("cp.async.wait_group 1;" ::: "memory")

// ---------------- kernel 1: spatial means ----------------
__global__ void mean_kernel(const float* __restrict__ q, const float* __restrict__ k) {
    int w    = blockIdx.x * (blockDim.x >> 5) + (threadIdx.x >> 5);
    int lane = threadIdx.x & 31;
    const int NROW = 64*DIM_;
    const float* src; float* dst; int r;
    if (w < NROW) { src = q; dst = g_qm; r = w; }
    else          { src = k; dst = g_km; r = w - NROW; }
    const float4* p = (const float4*)(src + (size_t)r * HW_);
    float s = 0.f;
#pragma unroll
    for (int i = 0; i < 8; i++) { float4 v4 = p[lane + i*32]; s += v4.x + v4.y + v4.z + v4.w; }
#pragma unroll
    for (int m = 16; m; m >>= 1) s += __shfl_xor_sync(0xffffffffu, s, m);
    if (lane == 0) dst[r] = s * (1.f/1024.f);
}

// ---------------- kernel 2: pooled projections ----------------
__global__ void proj_kernel(const float* __restrict__ Wq, const float* __restrict__ Wk) {
    __shared__ float rowS[DIM_];
    __shared__ float Ws[DIM_*17];
    int rr  = blockIdx.x;
    int tid = threadIdx.x;
    const float* W; const float* in; float* out; float scale;
    if (rr < 64) { in = g_qm + rr*DIM_;      W = Wq; out = g_qp + rr*DIM_;      scale = 0.125f; }
    else         { in = g_km + (rr-64)*DIM_; W = Wk; out = g_kp + (rr-64)*DIM_; scale = 1.f;    }
    rowS[tid] = in[tid];
    float acc = 0.f;
    for (int e0 = 0; e0 < DIM_; e0 += 16) {
        __syncthreads();
#pragma unroll
        for (int i = 0; i < 16; i++) {
            int idx = tid + i*512;
            int d = idx >> 4, e = idx & 15;
            Ws[d*17 + e] = W[d*DIM_ + e0 + e];
        }
        __syncthreads();
#pragma unroll
        for (int e = 0; e < 16; e++) acc += rowS[e0 + e] * Ws[tid*17 + e];
    }
    out[tid] = acc * scale;
}

// ---------------- kernel 3: softmax ----------------
__global__ void attn_kernel() {
    int blk = blockIdx.x;
    int b = blk >> 7, h = (blk >> 4) & 7, s = blk & 15;
    int lane = threadIdx.x, t = lane & 15;
    const float* qr = g_qp + (size_t)(b*16 + s)*DIM_ + h*64;
    const float* kr = g_kp + (size_t)(b*16 + t)*DIM_ + h*64;
    float lg = 0.f;
#pragma unroll
    for (int j = 0; j < 64; j++) lg += qr[j] * kr[j];
    float mx = lg;
#pragma unroll
    for (int m = 8; m; m >>= 1) mx = fmaxf(mx, __shfl_xor_sync(0xffffffffu, mx, m));
    float e = __expf(lg - mx);
    float sm = e;
#pragma unroll
    for (int m = 8; m; m >>= 1) sm += __shfl_xor_sync(0xffffffffu, sm, m);
    if (lane < 16) g_attn[((b*8 + h)*16 + s)*16 + t] = e / sm;
}

// ---------------- kernel 4: Wv -> fp16 hi/lo interleaved per 64-k chunk ----------------
__global__ void wvsplit_kernel(const float* __restrict__ Wv) {
    int g  = blockIdx.x * 512 + threadIdx.x;       // 0..32767
    int d  = g >> 6, k8 = (g & 63) * 8;
    const float* src = Wv + d*512 + k8;
    unsigned short hs[8], ls[8];
#pragma unroll
    for (int j = 0; j < 8; j++) {
        float x = src[j];
        __half h = __float2half_rn(x);
        __half l = __float2half_rn(x - __half2float(h));
        hs[j] = __half_as_ushort(h);
        ls[j] = __half_as_ushort(l);
    }
    int ch = k8 >> 6, pos = k8 & 63;
    size_t e = (size_t)d*1024 + ch*128 + pos;
    unsigned int hw[4], lw[4];
#pragma unroll
    for (int j = 0; j < 4; j++) {
        hw[j] = ((unsigned)hs[2*j+1] << 16) | hs[2*j];
        lw[j] = ((unsigned)ls[2*j+1] << 16) | ls[2*j];
    }
    *(uint4*)(g_wvs + e)      = make_uint4(hw[0], hw[1], hw[2], hw[3]);
    *(uint4*)(g_wvs + e + 64) = make_uint4(lw[0], lw[1], lw[2], lw[3]);
}

// ---------------- kernel 5: v transpose + fp16 convert ----------------
__global__ __launch_bounds__(256) void convert_kernel(const float* __restrict__ v) {
    __shared__ float st[64*65];
    int pb = blockIdx.x, kb = blockIdx.y, bt = blockIdx.z;
#pragma unroll
    for (int i = 0; i < 4; i++) {
        int idx = threadIdx.x + i*256;
        int kk = idx >> 4, p4 = (idx & 15) * 4;
        float4 x = *(const float4*)(v + ((size_t)(bt*512 + kb*64 + kk))*HW_ + pb*64 + p4);
        st[kk*65 + p4 + 0] = x.x; st[kk*65 + p4 + 1] = x.y;
        st[kk*65 + p4 + 2] = x.z; st[kk*65 + p4 + 3] = x.w;
    }
    __syncthreads();
#pragma unroll
    for (int it = 0; it < 2; it++) {
        int task = threadIdx.x + it*256;
        int p = task >> 3, kg = task & 7;
        unsigned int w[4];
#pragma unroll
        for (int j = 0; j < 4; j++) {
            unsigned short u0 = __half_as_ushort(__float2half_rn(st[(kg*8 + 2*j    )*65 + p]));
            unsigned short u1 = __half_as_ushort(__float2half_rn(st[(kg*8 + 2*j + 1)*65 + p]));
            w[j] = ((unsigned)u1 << 16) | u0;
        }
        size_t e = ((size_t)(bt*HW_ + pb*64 + p))*512 + kb*64 + kg*8;
        *(uint4*)(g_vs + e) = make_uint4(w[0], w[1], w[2], w[3]);
    }
}

// ---------------- kernel 6: pipelined warp-mma GEMM (fp16 2-term) + fused mix ----------------
// CTA: M=128 d x N=128 (16t x 8p) x K=512 in 8 chunks of 64, 2-stage cp.async.
// Stage (48KB): A[128r x 256B (hi64|lo64)] @0, B[128r x 128B] @32KB.
// Epilogue Cs[128n][132] fp32 aliases stages.
#define STG 49152
#define DSMEM (2*STG)
extern __shared__ char dsm[];

__global__ __launch_bounds__(256, 2) void gemm_kernel(float* __restrict__ out) {
    __shared__ float s_attnT[512];
    int tid = threadIdx.x, lane = tid & 31, wid = tid >> 5;
    int md = blockIdx.x & 3;
    int px = blockIdx.x >> 2;
    int b  = blockIdx.y;
    int sh0 = (px & 7) * 4, sw0 = (px >> 3) * 2;
    int d0 = md * 128;

    uint32_t sb = smem_u32(dsm);

#pragma unroll
    for (int i = 0; i < 2; i++) {
        int idx = tid + i*256;
        int hl = idx >> 8, tt = (idx >> 4) & 15, ss = idx & 15;
        s_attnT[idx] = g_attn[((b*8 + md*2 + hl)*16 + ss)*16 + tt];
    }

    // A: 2048 16B-blocks/stage -> 8 per thread; B: 1024 -> 4 per thread
    int soffA[8]; const __half* gA[8];
#pragma unroll
    for (int i = 0; i < 8; i++) {
        int idx = tid + i*256;              // 0..2047
        int r = idx >> 4, blk = idx & 15;
        soffA[i] = r*256 + (((blk ^ (r & 7))) << 4);
        gA[i]    = g_wvs + (size_t)(d0 + r)*1024 + blk*8;
    }
    int soffB[4]; const __half* gB[4];
#pragma unroll
    for (int i = 0; i < 4; i++) {
        int idx = tid + i*256;              // 0..1023
        int r = idx >> 3, c = idx & 7;
        soffB[i] = r*128 + (((c ^ (r & 7))) << 4);
        int t = r >> 3, pp = r & 7, ww = pp >> 2, hh = pp & 3;
        int pin = (sh0 + hh)*32 + (sw0 + ww);
        gB[i]    = g_vs + (size_t)((b*16 + t)*HW_ + pin)*512 + c*8;
    }

    int m0w = (wid & 3) * 32;
    int n0w = (wid >> 2) * 64;
    float acc[2][8][4];
#pragma unroll
    for (int mt = 0; mt < 2; mt++)
#pragma unroll
        for (int nt = 0; nt < 8; nt++)
#pragma unroll
            for (int j = 0; j < 4; j++) acc[mt][nt][j] = 0.f;

    // prologue: chunks 0,1
#pragma unroll
    for (int c = 0; c < 2; c++) {
        uint32_t sa = sb + c*STG;
#pragma unroll
        for (int i = 0; i < 8; i++) cpa16(sa +         soffA[i], gA[i] + c*128);
#pragma unroll
        for (int i = 0; i < 4; i++) cpa16(sa + 32768 + soffB[i], gB[i] + c*64);
        CP_COMMIT();
    }

#pragma unroll 1
    for (int c = 0; c < 8; c++) {
        CP_WAIT1();
        __syncthreads();
        uint32_t sa  = sb + (c & 1)*STG;
        uint32_t sbb = sa + 32768;
#pragma unroll
        for (int ks = 0; ks < 4; ks++) {
            uint32_t ah[2][4], al[2][4];
            int arow_l = lane & 15;
            int asel   = lane >> 4;
            int ablk   = 2*ks + asel;
#pragma unroll
            for (int mt = 0; mt < 2; mt++) {
                int row = m0w + mt*16 + arow_l;
                uint32_t rb = sa + row*256;
                ldm_x4(ah[mt], rb + (((ablk    ) ^ (row & 7)) << 4));
                ldm_x4(al[mt], rb + (((ablk + 8) ^ (row & 7)) << 4));
            }
            int brow_l = (lane & 7) + ((lane & 16) ? 8 : 0);
            int bblk   = 2*ks + ((lane >> 3) & 1);
#pragma unroll
            for (int ntp = 0; ntp < 4; ntp++) {
                int row = n0w + ntp*16 + brow_l;
                uint32_t bh[4];
                ldm_x4(bh, sbb + row*128 + ((bblk ^ (row & 7)) << 4));
#pragma unroll
                for (int mt = 0; mt < 2; mt++) {
                    mma_f16(acc[mt][2*ntp  ], ah[mt], bh[0], bh[1]);
                    mma_f16(acc[mt][2*ntp  ], al[mt], bh[0], bh[1]);
                    mma_f16(acc[mt][2*ntp+1], ah[mt], bh[2], bh[3]);
                    mma_f16(acc[mt][2*ntp+1], al[mt], bh[2], bh[3]);
                }
            }
        }
        __syncthreads();
        if (c + 2 < 8) {
            uint32_t sd = sb + (c & 1)*STG;
#pragma unroll
            for (int i = 0; i < 8; i++) cpa16(sd +         soffA[i], gA[i] + (c+2)*128);
#pragma unroll
            for (int i = 0; i < 4; i++) cpa16(sd + 32768 + soffB[i], gB[i] + (c+2)*64);
        }
        CP_COMMIT();
    }

    // store accumulators: Cs[n][d], stride 132 (aliases stage buffers)
    float* Cs = (float*)dsm;
    int g = lane >> 2, tig = lane & 3;
#pragma unroll
    for (int mt = 0; mt < 2; mt++)
#pragma unroll
        for (int nt = 0; nt < 8; nt++) {
            int m = m0w + mt*16 + g;
            int n = n0w + nt*8 + 2*tig;
            Cs[n*132 + m]         = acc[mt][nt][0];
            Cs[(n+1)*132 + m]     = acc[mt][nt][1];
            Cs[n*132 + m + 8]     = acc[mt][nt][2];
            Cs[(n+1)*132 + m + 8] = acc[mt][nt][3];
        }
    __syncthreads();

    // mix epilogue
    {
        int d = tid & 127, ww = tid >> 7;
        int hl = d >> 6;
        const float* at = s_attnT + hl*256;
        unsigned long long ap[16][2];
#pragma unroll
        for (int s = 0; s < 16; s++) { ap[s][0] = 0ull; ap[s][1] = 0ull; }
#pragma unroll
        for (int t = 0; t < 16; t++) {
            float c0 = Cs[(t*8 + ww*4 + 0)*132 + d];
            float c1 = Cs[(t*8 + ww*4 + 1)*132 + d];
            float c2 = Cs[(t*8 + ww*4 + 2)*132 + d];
            float c3 = Cs[(t*8 + ww*4 + 3)*132 + d];
            unsigned long long cv01 = ((unsigned long long)__float_as_uint(c1) << 32) | __float_as_uint(c0);
            unsigned long long cv23 = ((unsigned long long)__float_as_uint(c3) << 32) | __float_as_uint(c2);
#pragma unroll
            for (int s = 0; s < 16; s++) {
                unsigned int wu = __float_as_uint(at[t*16 + s]);
                unsigned long long w2 = ((unsigned long long)wu << 32) | wu;
                asm("fma.rn.f32x2 %0, %1, %2, %0;" : "+l"(ap[s][0]) : "l"(cv01), "l"(w2));
                asm("fma.rn.f32x2 %0, %1, %2, %0;" : "+l"(ap[s][1]) : "l"(cv23), "l"(w2));
            }
        }
        float* op = out + ((size_t)(b*16)*512 + d0 + d)*HW_ + (sw0 + ww)*32 + sh0;
#pragma unroll
        for (int s = 0; s < 16; s++) {
            float4 v4;
            v4.x = __uint_as_float((unsigned int)(ap[s][0] & 0xffffffffull));
            v4.y = __uint_as_float((unsigned int)(ap[s][0] >> 32));
            v4.z = __uint_as_float((unsigned int)(ap[s][1] & 0xffffffffull));
            v4.w = __uint_as_float((unsigned int)(ap[s][1] >> 32));
            *(float4*)(op + (size_t)s*512*HW_) = v4;
        }
    }
}

// ---------------- launcher ----------------
extern "C" void kernel_launch(void* const* d_in, const int* in_sizes, int n_in,
                              void* d_out, int out_size) {
    const float* q  = (const float*)d_in[0];
    const float* k  = (const float*)d_in[1];
    const float* v  = (const float*)d_in[2];
    const float* Wq = (const float*)d_in[3];
    const float* Wk = (const float*)d_in[4];
    const float* Wv = (const float*)d_in[5];
    float* out = (float*)d_out;

    cudaFuncSetAttribute(gemm_kernel, cudaFuncAttributeMaxDynamicSharedMemorySize, DSMEM);

    mean_kernel<<<8192, 256>>>(q, k);
    proj_kernel<<<128, 512>>>(Wq, Wk);
    attn_kernel<<<512, 32>>>();
    wvsplit_kernel<<<64, 512>>>(Wv);
    dim3 gc(16, 8, 64);
    convert_kernel<<<gc, 256>>>(v);
    dim3 gg(512, 4);
    gemm_kernel<<<gg, 256, DSMEM>>>(out);
}

// round 9
// speedup vs baseline: 7.4682x; 1.2870x over previous
#include <cuda_runtime.h>
#include <cuda_fp16.h>
#include <cstdint>

#define B_     4
#define DIM_   512
#define HW_    1024

// ---------------- scratch ----------------
__device__ float g_qm[64*DIM_];
__device__ float g_km[64*DIM_];
__device__ float g_qp[64*DIM_];
__device__ float g_kp[64*DIM_];
__device__ float g_attn[B_*8*16*16];
__device__ __half g_wv16[DIM_*DIM_];          // [d][k] fp16
__device__ __half g_vs[64ull*HW_*DIM_];       // [bt][p][k] fp16

__device__ __forceinline__ uint32_t smem_u32(const void* p) {
    uint32_t a;
    asm("{ .reg .u64 t; cvta.to.shared.u64 t, %1; cvt.u32.u64 %0, t; }" : "=r"(a) : "l"(p));
    return a;
}
__device__ __forceinline__ void ldm_x4(uint32_t* r, uint32_t addr) {
    asm volatile("ldmatrix.sync.aligned.m8n8.x4.shared.b16 {%0,%1,%2,%3}, [%4];"
                 : "=r"(r[0]), "=r"(r[1]), "=r"(r[2]), "=r"(r[3]) : "r"(addr));
}
__device__ __forceinline__ void mma_f16(float* c, const uint32_t* a, uint32_t b0, uint32_t b1) {
    asm volatile("mma.sync.aligned.m16n8k16.row.col.f32.f16.f16.f32 "
        "{%0,%1,%2,%3}, {%4,%5,%6,%7}, {%8,%9}, {%0,%1,%2,%3};"
        : "+f"(c[0]), "+f"(c[1]), "+f"(c[2]), "+f"(c[3])
        : "r"(a[0]), "r"(a[1]), "r"(a[2]), "r"(a[3]), "r"(b0), "r"(b1));
}
__device__ __forceinline__ void cpa16(uint32_t d, const void* s) {
    asm volatile("cp.async.cg.shared.global [%0], [%1], 16;"
                 :: "r"(d), "l"(__cvta_generic_to_global(s)));
}
#define CP_COMMIT() asm volatile("cp.async.commit_group;" ::: "memory")
#define CP_WAIT2()  asm volatile("cp.async.wait_group 2;" ::: "memory")

// ---------------- kernel 1: spatial means ----------------
__global__ void mean_kernel(const float* __restrict__ q, const float* __restrict__ k) {
    int w    = blockIdx.x * (blockDim.x >> 5) + (threadIdx.x >> 5);
    int lane = threadIdx.x & 31;
    const int NROW = 64*DIM_;
    const float* src; float* dst; int r;
    if (w < NROW) { src = q; dst = g_qm; r = w; }
    else          { src = k; dst = g_km; r = w - NROW; }
    const float4* p = (const float4*)(src + (size_t)r * HW_);
    float s = 0.f;
#pragma unroll
    for (int i = 0; i < 8; i++) { float4 v4 = p[lane + i*32]; s += v4.x + v4.y + v4.z + v4.w; }
#pragma unroll
    for (int m = 16; m; m >>= 1) s += __shfl_xor_sync(0xffffffffu, s, m);
    if (lane == 0) dst[r] = s * (1.f/1024.f);
}

// ---------------- kernel 2: pooled projections ----------------
__global__ void proj_kernel(const float* __restrict__ Wq, const float* __restrict__ Wk) {
    __shared__ float rowS[DIM_];
    __shared__ float Ws[DIM_*17];
    int rr  = blockIdx.x;
    int tid = threadIdx.x;
    const float* W; const float* in; float* out; float scale;
    if (rr < 64) { in = g_qm + rr*DIM_;      W = Wq; out = g_qp + rr*DIM_;      scale = 0.125f; }
    else         { in = g_km + (rr-64)*DIM_; W = Wk; out = g_kp + (rr-64)*DIM_; scale = 1.f;    }
    rowS[tid] = in[tid];
    float acc = 0.f;
    for (int e0 = 0; e0 < DIM_; e0 += 16) {
        __syncthreads();
#pragma unroll
        for (int i = 0; i < 16; i++) {
            int idx = tid + i*512;
            int d = idx >> 4, e = idx & 15;
            Ws[d*17 + e] = W[d*DIM_ + e0 + e];
        }
        __syncthreads();
#pragma unroll
        for (int e = 0; e < 16; e++) acc += rowS[e0 + e] * Ws[tid*17 + e];
    }
    out[tid] = acc * scale;
}

// ---------------- kernel 3: softmax ----------------
__global__ void attn_kernel() {
    int blk = blockIdx.x;
    int b = blk >> 7, h = (blk >> 4) & 7, s = blk & 15;
    int lane = threadIdx.x, t = lane & 15;
    const float* qr = g_qp + (size_t)(b*16 + s)*DIM_ + h*64;
    const float* kr = g_kp + (size_t)(b*16 + t)*DIM_ + h*64;
    float lg = 0.f;
#pragma unroll
    for (int j = 0; j < 64; j++) lg += qr[j] * kr[j];
    float mx = lg;
#pragma unroll
    for (int m = 8; m; m >>= 1) mx = fmaxf(mx, __shfl_xor_sync(0xffffffffu, mx, m));
    float e = __expf(lg - mx);
    float sm = e;
#pragma unroll
    for (int m = 8; m; m >>= 1) sm += __shfl_xor_sync(0xffffffffu, sm, m);
    if (lane < 16) g_attn[((b*8 + h)*16 + s)*16 + t] = e / sm;
}

// ---------------- kernel 4: Wv -> fp16 ----------------
__global__ void wvconv_kernel(const float* __restrict__ Wv) {
    int g = blockIdx.x * 512 + threadIdx.x;        // 0..32767
    const float* src = Wv + g*8;
    unsigned int w[4];
#pragma unroll
    for (int j = 0; j < 4; j++) {
        unsigned short u0 = __half_as_ushort(__float2half_rn(src[2*j]));
        unsigned short u1 = __half_as_ushort(__float2half_rn(src[2*j+1]));
        w[j] = ((unsigned)u1 << 16) | u0;
    }
    *(uint4*)(g_wv16 + (size_t)g*8) = make_uint4(w[0], w[1], w[2], w[3]);
}

// ---------------- kernel 5: v transpose + fp16 convert ----------------
__global__ __launch_bounds__(256) void convert_kernel(const float* __restrict__ v) {
    __shared__ float st[64*65];
    int pb = blockIdx.x, kb = blockIdx.y, bt = blockIdx.z;
#pragma unroll
    for (int i = 0; i < 4; i++) {
        int idx = threadIdx.x + i*256;
        int kk = idx >> 4, p4 = (idx & 15) * 4;
        float4 x = *(const float4*)(v + ((size_t)(bt*512 + kb*64 + kk))*HW_ + pb*64 + p4);
        st[kk*65 + p4 + 0] = x.x; st[kk*65 + p4 + 1] = x.y;
        st[kk*65 + p4 + 2] = x.z; st[kk*65 + p4 + 3] = x.w;
    }
    __syncthreads();
#pragma unroll
    for (int it = 0; it < 2; it++) {
        int task = threadIdx.x + it*256;
        int p = task >> 3, kg = task & 7;
        unsigned int w[4];
#pragma unroll
        for (int j = 0; j < 4; j++) {
            unsigned short u0 = __half_as_ushort(__float2half_rn(st[(kg*8 + 2*j    )*65 + p]));
            unsigned short u1 = __half_as_ushort(__float2half_rn(st[(kg*8 + 2*j + 1)*65 + p]));
            w[j] = ((unsigned)u1 << 16) | u0;
        }
        size_t e = ((size_t)(bt*HW_ + pb*64 + p))*512 + kb*64 + kg*8;
        *(uint4*)(g_vs + e) = make_uint4(w[0], w[1], w[2], w[3]);
    }
}

// ---------------- kernel 6: pipelined warp-mma GEMM (single-term fp16) + fused mix ----------------
// CTA: M=128 d x N=128 (16t x 8p) x K=512 in 8 chunks of 64, 3-stage cp.async.
// Stage (32KB): A[128r x 128B] @0, B[128r x 128B] @16KB. Cs[128n][132] fp32 aliases stages.
#define STG 32768
#define DSMEM (3*STG)
extern __shared__ char dsm[];

__global__ __launch_bounds__(256, 2) void gemm_kernel(float* __restrict__ out) {
    __shared__ float s_attnT[512];
    int tid = threadIdx.x, lane = tid & 31, wid = tid >> 5;
    int md = blockIdx.x & 3;
    int px = blockIdx.x >> 2;
    int b  = blockIdx.y;
    int sh0 = (px & 7) * 4, sw0 = (px >> 3) * 2;
    int d0 = md * 128;

    uint32_t sb = smem_u32(dsm);

#pragma unroll
    for (int i = 0; i < 2; i++) {
        int idx = tid + i*256;
        int hl = idx >> 8, tt = (idx >> 4) & 15, ss = idx & 15;
        s_attnT[idx] = g_attn[((b*8 + md*2 + hl)*16 + ss)*16 + tt];
    }

    // A and B: 1024 16B-blocks per stage each -> 4 per thread
    int soff[4]; const __half* gA[4]; const __half* gB[4];
#pragma unroll
    for (int i = 0; i < 4; i++) {
        int idx = tid + i*256;              // 0..1023
        int r = idx >> 3, c = idx & 7;
        soff[i] = r*128 + (((c ^ (r & 7))) << 4);
        gA[i]   = g_wv16 + (size_t)(d0 + r)*512 + c*8;
        int t = r >> 3, pp = r & 7, ww = pp >> 2, hh = pp & 3;
        int pin = (sh0 + hh)*32 + (sw0 + ww);
        gB[i]   = g_vs + (size_t)((b*16 + t)*HW_ + pin)*512 + c*8;
    }

    int m0w = (wid & 3) * 32;
    int n0w = (wid >> 2) * 64;
    float acc[2][8][4];
#pragma unroll
    for (int mt = 0; mt < 2; mt++)
#pragma unroll
        for (int nt = 0; nt < 8; nt++)
#pragma unroll
            for (int j = 0; j < 4; j++) acc[mt][nt][j] = 0.f;

    // prologue: chunks 0..2
#pragma unroll
    for (int c = 0; c < 3; c++) {
        uint32_t sa = sb + c*STG;
#pragma unroll
        for (int i = 0; i < 4; i++) {
            cpa16(sa +         soff[i], gA[i] + c*64);
            cpa16(sa + 16384 + soff[i], gB[i] + c*64);
        }
        CP_COMMIT();
    }

    int stg = 0;
#pragma unroll 1
    for (int c = 0; c < 8; c++) {
        CP_WAIT2();
        __syncthreads();
        uint32_t sa  = sb + stg*STG;
        uint32_t sbb = sa + 16384;
#pragma unroll
        for (int ks = 0; ks < 4; ks++) {
            uint32_t ah[2][4];
            int arow_l = lane & 15;
            int ablk   = 2*ks + (lane >> 4);
#pragma unroll
            for (int mt = 0; mt < 2; mt++) {
                int row = m0w + mt*16 + arow_l;
                ldm_x4(ah[mt], sa + row*128 + ((ablk ^ (row & 7)) << 4));
            }
            int brow_l = (lane & 7) + ((lane & 16) ? 8 : 0);
            int bblk   = 2*ks + ((lane >> 3) & 1);
#pragma unroll
            for (int ntp = 0; ntp < 4; ntp++) {
                int row = n0w + ntp*16 + brow_l;
                uint32_t bh[4];
                ldm_x4(bh, sbb + row*128 + ((bblk ^ (row & 7)) << 4));
#pragma unroll
                for (int mt = 0; mt < 2; mt++) {
                    mma_f16(acc[mt][2*ntp  ], ah[mt], bh[0], bh[1]);
                    mma_f16(acc[mt][2*ntp+1], ah[mt], bh[2], bh[3]);
                }
            }
        }
        __syncthreads();
        if (c + 3 < 8) {
            uint32_t sd = sb + stg*STG;
#pragma unroll
            for (int i = 0; i < 4; i++) {
                cpa16(sd +         soff[i], gA[i] + (c+3)*64);
                cpa16(sd + 16384 + soff[i], gB[i] + (c+3)*64);
            }
        }
        CP_COMMIT();
        stg = (stg + 1) == 3 ? 0 : stg + 1;
    }

    // store accumulators: Cs[n][d], stride 132 (aliases stage buffers)
    float* Cs = (float*)dsm;
    int g = lane >> 2, tig = lane & 3;
#pragma unroll
    for (int mt = 0; mt < 2; mt++)
#pragma unroll
        for (int nt = 0; nt < 8; nt++) {
            int m = m0w + mt*16 + g;
            int n = n0w + nt*8 + 2*tig;
            Cs[n*132 + m]         = acc[mt][nt][0];
            Cs[(n+1)*132 + m]     = acc[mt][nt][1];
            Cs[n*132 + m + 8]     = acc[mt][nt][2];
            Cs[(n+1)*132 + m + 8] = acc[mt][nt][3];
        }
    __syncthreads();

    // mix epilogue
    {
        int d = tid & 127, ww = tid >> 7;
        int hl = d >> 6;
        const float* at = s_attnT + hl*256;
        unsigned long long ap[16][2];
#pragma unroll
        for (int s = 0; s < 16; s++) { ap[s][0] = 0ull; ap[s][1] = 0ull; }
#pragma unroll
        for (int t = 0; t < 16; t++) {
            float c0 = Cs[(t*8 + ww*4 + 0)*132 + d];
            float c1 = Cs[(t*8 + ww*4 + 1)*132 + d];
            float c2 = Cs[(t*8 + ww*4 + 2)*132 + d];
            float c3 = Cs[(t*8 + ww*4 + 3)*132 + d];
            unsigned long long cv01 = ((unsigned long long)__float_as_uint(c1) << 32) | __float_as_uint(c0);
            unsigned long long cv23 = ((unsigned long long)__float_as_uint(c3) << 32) | __float_as_uint(c2);
#pragma unroll
            for (int s = 0; s < 16; s++) {
                unsigned int wu = __float_as_uint(at[t*16 + s]);
                unsigned long long w2 = ((unsigned long long)wu << 32) | wu;
                asm("fma.rn.f32x2 %0, %1, %2, %0;" : "+l"(ap[s][0]) : "l"(cv01), "l"(w2));
                asm("fma.rn.f32x2 %0, %1, %2, %0;" : "+l"(ap[s][1]) : "l"(cv23), "l"(w2));
            }
        }
        float* op = out + ((size_t)(b*16)*512 + d0 + d)*HW_ + (sw0 + ww)*32 + sh0;
#pragma unroll
        for (int s = 0; s < 16; s++) {
            float4 v4;
            v4.x = __uint_as_float((unsigned int)(ap[s][0] & 0xffffffffull));
            v4.y = __uint_as_float((unsigned int)(ap[s][0] >> 32));
            v4.z = __uint_as_float((unsigned int)(ap[s][1] & 0xffffffffull));
            v4.w = __uint_as_float((unsigned int)(ap[s][1] >> 32));
            *(float4*)(op + (size_t)s*512*HW_) = v4;
        }
    }
}

// ---------------- launcher ----------------
extern "C" void kernel_launch(void* const* d_in, const int* in_sizes, int n_in,
                              void* d_out, int out_size) {
    const float* q  = (const float*)d_in[0];
    const float* k  = (const float*)d_in[1];
    const float* v  = (const float*)d_in[2];
    const float* Wq = (const float*)d_in[3];
    const float* Wk = (const float*)d_in[4];
    const float* Wv = (const float*)d_in[5];
    float* out = (float*)d_out;

    cudaFuncSetAttribute(gemm_kernel, cudaFuncAttributeMaxDynamicSharedMemorySize, DSMEM);

    mean_kernel<<<8192, 256>>>(q, k);
    proj_kernel<<<128, 512>>>(Wq, Wk);
    attn_kernel<<<512, 32>>>();
    wvconv_kernel<<<64, 512>>>(Wv);
    dim3 gc(16, 8, 64);
    convert_kernel<<<gc, 256>>>(v);
    dim3 gg(512, 4);
    gemm_kernel<<<gg, 256, DSMEM>>>(out);
}